// round 9
// baseline (speedup 1.0000x reference)
#include <cuda_runtime.h>

// GCNConv on GB300: out = relu(D^-1/2 (A+I) D^-1/2 (X W) + b), edge-weighted.
// R9: warp-per-node gather-reduce. Two 16-lane sides each take every other
// edge with 4-wide ILP (4 gathers in flight), combined by shfl_xor(16).
// Halves per-node serial latency vs half-warp-per-node and removes
// cross-node divergence inside a warp. CSR build = R8 packed-atomic bins.

constexpr int N_NODES = 100000;
constexpr int N_EDGES = 1600000;
constexpr int F_IN    = 128;
constexpr int F_OUT   = 64;
constexpr int CAP     = 64;       // per-node bin capacity (deg ~ Poisson(16))

typedef unsigned long long ull;

constexpr ull  DEG_MASK = (1ULL << 40) - 1;
constexpr float DEG_SCALE_INV = 1.0f / 4294967296.0f;   // 2^-32

__device__ __align__(16) float g_dis[N_NODES];
__device__ __align__(16) float g_xs[(size_t)N_NODES * F_OUT];
__device__ ull  g_pack[N_NODES];                         // (cnt<<40)|fx_deg
__device__ __align__(16) int2 g_sw[(size_t)N_NODES * CAP];   // 51.2 MB bins

__device__ __forceinline__ ull pack2(float x) {
    ull r; asm("mov.b64 %0, {%1, %1};" : "=l"(r) : "f"(x)); return r;
}
__device__ __forceinline__ void fma2(ull& d, ull a, ull b) {
    asm("fma.rn.f32x2 %0, %1, %2, %0;" : "+l"(d) : "l"(a), "l"(b));
}
__device__ __forceinline__ ull mul2(ull a, ull b) {
    ull r; asm("mul.rn.f32x2 %0, %1, %2;" : "=l"(r) : "l"(a), "l"(b)); return r;
}

// ---------------------------------------------------------------------------
// K0: zero the packed counters.
__global__ void k_init() {
    int i = blockIdx.x * blockDim.x + threadIdx.x;
    if (i < N_NODES) g_pack[i] = 0ULL;
}

// ---------------------------------------------------------------------------
// K1: single edge pass, ONE packed 64-bit atomic per edge.
// rank = old>>40; low 40 bits accumulate w in 2^32 fixed point.
constexpr int EH = N_EDGES / 2;   // 800000
__global__ void k_deg(const int* __restrict__ row, const int* __restrict__ col,
                      const float* __restrict__ w) {
    int t = blockIdx.x * blockDim.x + threadIdx.x;
    if (t >= EH) return;
    int e0 = t, e1 = t + EH;
    int c0 = __ldg(col + e0), c1 = __ldg(col + e1);
    int r0 = __ldg(row + e0), r1 = __ldg(row + e1);
    float w0 = __ldg(w + e0), w1 = __ldg(w + e1);
    ull a0 = (1ULL << 40) | (ull)(w0 * 4294967296.0f);
    ull a1 = (1ULL << 40) | (ull)(w1 * 4294967296.0f);
    ull o0 = atomicAdd(&g_pack[c0], a0);
    ull o1 = atomicAdd(&g_pack[c1], a1);
    int p0 = (int)(o0 >> 40);
    int p1 = (int)(o1 >> 40);
    g_sw[(size_t)c0 * CAP + p0] = make_int2(r0, __float_as_int(w0));
    g_sw[(size_t)c1 * CAP + p1] = make_int2(r1, __float_as_int(w1));
}

// ---------------------------------------------------------------------------
// K2: xs = dis * (X @ W), f32x2 register-blocked GEMM (proven).
constexpr int GEMM_TPB = 256;
constexpr int NPB      = 128;
constexpr int KC       = 32;

__global__ __launch_bounds__(GEMM_TPB)
void k_gemm(const float* __restrict__ X, const float* __restrict__ W) {
    __shared__ float sW[F_IN * F_OUT];   // 32 KB
    __shared__ float sX[NPB * KC];       // 16 KB

    const int tid  = threadIdx.x;
    const int g    = tid & 7;
    const int slot = tid >> 3;
    const int nb   = blockIdx.x * NPB;
    const int ln0  = slot * 4;

    for (int i = tid; i < F_IN * F_OUT / 4; i += GEMM_TPB)
        reinterpret_cast<float4*>(sW)[i] = reinterpret_cast<const float4*>(W)[i];

    ull acc[4][4];
    #pragma unroll
    for (int i = 0; i < 4; i++)
        #pragma unroll
        for (int j = 0; j < 4; j++) acc[i][j] = 0ull;

    for (int c = 0; c < F_IN / KC; c++) {
        __syncthreads();
        for (int i = tid; i < NPB * KC / 4; i += GEMM_TPB) {
            int node = i >> 3;
            int kq   = i & 7;
            float4 v = make_float4(0.f, 0.f, 0.f, 0.f);
            int gn = nb + node;
            if (gn < N_NODES)
                v = reinterpret_cast<const float4*>(X)[(size_t)gn * (F_IN / 4) + c * 8 + kq];
            int k0 = kq * 4;
            sX[node * KC + (((k0 + 0) ^ node) & 31)] = v.x;
            sX[node * KC + (((k0 + 1) ^ node) & 31)] = v.y;
            sX[node * KC + (((k0 + 2) ^ node) & 31)] = v.z;
            sX[node * KC + (((k0 + 3) ^ node) & 31)] = v.w;
        }
        __syncthreads();

        #pragma unroll
        for (int kk = 0; kk < KC; kk++) {
            int row = c * KC + kk;
            ulonglong2 wa = reinterpret_cast<ulonglong2*>(sW)[row * 16 + g * 2];
            ulonglong2 wb = reinterpret_cast<ulonglong2*>(sW)[row * 16 + g * 2 + 1];
            #pragma unroll
            for (int i = 0; i < 4; i++) {
                int ln = ln0 + i;
                float x = sX[ln * KC + ((kk ^ ln) & 31)];
                ull xx = pack2(x);
                fma2(acc[i][0], xx, wa.x);
                fma2(acc[i][1], xx, wa.y);
                fma2(acc[i][2], xx, wb.x);
                fma2(acc[i][3], xx, wb.y);
            }
        }
    }

    #pragma unroll
    for (int i = 0; i < 4; i++) {
        int gn = nb + ln0 + i;
        if (gn < N_NODES) {
            float deg = (float)(g_pack[gn] & DEG_MASK) * DEG_SCALE_INV;
            float d = rsqrtf(deg + 1.0f);
            if (g == 0) g_dis[gn] = d;
            ull dd = pack2(d);
            ulonglong2 o0, o1;
            o0.x = mul2(acc[i][0], dd); o0.y = mul2(acc[i][1], dd);
            o1.x = mul2(acc[i][2], dd); o1.y = mul2(acc[i][3], dd);
            reinterpret_cast<ulonglong2*>(g_xs)[(size_t)gn * 16 + g * 2]     = o0;
            reinterpret_cast<ulonglong2*>(g_xs)[(size_t)gn * 16 + g * 2 + 1] = o1;
        }
    }
}

// ---------------------------------------------------------------------------
// K3: warp-per-node gather-reduce + fused epilogue.
// Side s (lanes s*16..s*16+15) handles edges e = 2k+s, 4-wide unrolled.
// Feature quad q = lane&15. Combine sides with shfl_xor(16); side 0 writes.
__global__ __launch_bounds__(256)
void k_agg(const float* __restrict__ b, float* __restrict__ out) {
    int t = blockIdx.x * blockDim.x + threadIdx.x;
    int node = t >> 5;
    int lane = t & 31;
    if (node >= N_NODES) return;
    const int s = lane >> 4;
    const int q = lane & 15;

    const int2* bin = g_sw + (size_t)node * CAP;
    const int cnt  = (int)(g_pack[node] >> 40);
    const int half = (cnt + 1 - s) >> 1;     // side-s edge count
    const float4* xs4 = reinterpret_cast<const float4*>(g_xs);

    float4 acc = make_float4(0.f, 0.f, 0.f, 0.f);
    int k = 0;
    for (; k + 4 <= half; k += 4) {
        int j0 = 2 * k + s;
        int2 m0 = __ldg(bin + j0);
        int2 m1 = __ldg(bin + j0 + 2);
        int2 m2 = __ldg(bin + j0 + 4);
        int2 m3 = __ldg(bin + j0 + 6);
        float4 v0 = __ldg(&xs4[(size_t)m0.x * 16 + q]);
        float4 v1 = __ldg(&xs4[(size_t)m1.x * 16 + q]);
        float4 v2 = __ldg(&xs4[(size_t)m2.x * 16 + q]);
        float4 v3 = __ldg(&xs4[(size_t)m3.x * 16 + q]);
        float w0 = __int_as_float(m0.y), w1 = __int_as_float(m1.y);
        float w2 = __int_as_float(m2.y), w3 = __int_as_float(m3.y);
        acc.x = fmaf(w0, v0.x, acc.x); acc.y = fmaf(w0, v0.y, acc.y);
        acc.z = fmaf(w0, v0.z, acc.z); acc.w = fmaf(w0, v0.w, acc.w);
        acc.x = fmaf(w1, v1.x, acc.x); acc.y = fmaf(w1, v1.y, acc.y);
        acc.z = fmaf(w1, v1.z, acc.z); acc.w = fmaf(w1, v1.w, acc.w);
        acc.x = fmaf(w2, v2.x, acc.x); acc.y = fmaf(w2, v2.y, acc.y);
        acc.z = fmaf(w2, v2.z, acc.z); acc.w = fmaf(w2, v2.w, acc.w);
        acc.x = fmaf(w3, v3.x, acc.x); acc.y = fmaf(w3, v3.y, acc.y);
        acc.z = fmaf(w3, v3.z, acc.z); acc.w = fmaf(w3, v3.w, acc.w);
    }
    for (; k < half; k++) {
        int2 e = __ldg(bin + 2 * k + s);
        float4 v = __ldg(&xs4[(size_t)e.x * 16 + q]);
        float we = __int_as_float(e.y);
        acc.x = fmaf(we, v.x, acc.x); acc.y = fmaf(we, v.y, acc.y);
        acc.z = fmaf(we, v.z, acc.z); acc.w = fmaf(we, v.w, acc.w);
    }

    // Combine the two sides (feature quad q aligns across the xor).
    acc.x += __shfl_xor_sync(0xffffffffu, acc.x, 16);
    acc.y += __shfl_xor_sync(0xffffffffu, acc.y, 16);
    acc.z += __shfl_xor_sync(0xffffffffu, acc.z, 16);
    acc.w += __shfl_xor_sync(0xffffffffu, acc.w, 16);

    if (s == 0) {
        float  d  = g_dis[node];
        float4 x  = __ldg(&xs4[(size_t)node * 16 + q]);
        float4 bb = __ldg(&reinterpret_cast<const float4*>(b)[q]);
        float4 o;
        o.x = fmaxf(fmaf(d, acc.x + x.x, bb.x), 0.f);
        o.y = fmaxf(fmaf(d, acc.y + x.y, bb.y), 0.f);
        o.z = fmaxf(fmaf(d, acc.z + x.z, bb.z), 0.f);
        o.w = fmaxf(fmaf(d, acc.w + x.w, bb.w), 0.f);
        reinterpret_cast<float4*>(out)[(size_t)node * 16 + q] = o;
    }
}

// ---------------------------------------------------------------------------
extern "C" void kernel_launch(void* const* d_in, const int* in_sizes, int n_in,
                              void* d_out, int out_size) {
    const float* X  = (const float*)d_in[0];            // [N, 128]
    const int*   ei = (const int*)d_in[1];              // [2, E]
    const float* w  = (const float*)d_in[2];            // [E]
    const float* W  = (const float*)d_in[3];            // [128, 64]
    const float* b  = (const float*)d_in[4];            // [64]
    float* out = (float*)d_out;                         // [N, 64]

    const int* row = ei;                // sources
    const int* col = ei + N_EDGES;      // targets

    k_init<<<(N_NODES + 255) / 256, 256>>>();
    k_deg <<<(EH + 255) / 256, 256>>>(row, col, w);
    {   int grid = (N_NODES + NPB - 1) / NPB;
        k_gemm<<<grid, GEMM_TPB>>>(X, W); }
    {   long long threads = (long long)N_NODES * 32;
        k_agg<<<(int)((threads + 255) / 256), 256>>>(b, out); }
}

// round 10
// speedup vs baseline: 1.0259x; 1.0259x over previous
#include <cuda_runtime.h>

// GCNConv on GB300: out = relu(D^-1/2 (A+I) D^-1/2 (X W) + b), edge-weighted.
// R10 = proven-best recombination:
//   - R8 CSR build: ONE packed 64-bit atomic per edge
//     (rank in bits [40:64), 2^32 fixed-point weighted degree in [0:40)).
//   - R7 gather-reduce: half-warp per node, contiguous int2 meta, 4-wide ILP
//     (44.3us measured; 8-wide and warp-per-node variants both regressed).

constexpr int N_NODES = 100000;
constexpr int N_EDGES = 1600000;
constexpr int F_IN    = 128;
constexpr int F_OUT   = 64;
constexpr int CAP     = 64;       // per-node bin capacity (deg ~ Poisson(16))

typedef unsigned long long ull;

constexpr ull  DEG_MASK = (1ULL << 40) - 1;
constexpr float DEG_SCALE_INV = 1.0f / 4294967296.0f;   // 2^-32

__device__ __align__(16) float g_dis[N_NODES];
__device__ __align__(16) float g_xs[(size_t)N_NODES * F_OUT];
__device__ ull  g_pack[N_NODES];                         // (cnt<<40)|fx_deg
__device__ __align__(16) int2 g_sw[(size_t)N_NODES * CAP];   // 51.2 MB bins

__device__ __forceinline__ ull pack2(float x) {
    ull r; asm("mov.b64 %0, {%1, %1};" : "=l"(r) : "f"(x)); return r;
}
__device__ __forceinline__ void fma2(ull& d, ull a, ull b) {
    asm("fma.rn.f32x2 %0, %1, %2, %0;" : "+l"(d) : "l"(a), "l"(b));
}
__device__ __forceinline__ ull mul2(ull a, ull b) {
    ull r; asm("mul.rn.f32x2 %0, %1, %2;" : "=l"(r) : "l"(a), "l"(b)); return r;
}

// ---------------------------------------------------------------------------
// K0: zero the packed counters.
__global__ void k_init() {
    int i = blockIdx.x * blockDim.x + threadIdx.x;
    if (i < N_NODES) g_pack[i] = 0ULL;
}

// ---------------------------------------------------------------------------
// K1: single edge pass, ONE packed 64-bit atomic per edge.
constexpr int EH = N_EDGES / 2;   // 800000
__global__ void k_deg(const int* __restrict__ row, const int* __restrict__ col,
                      const float* __restrict__ w) {
    int t = blockIdx.x * blockDim.x + threadIdx.x;
    if (t >= EH) return;
    int e0 = t, e1 = t + EH;
    int c0 = __ldg(col + e0), c1 = __ldg(col + e1);
    int r0 = __ldg(row + e0), r1 = __ldg(row + e1);
    float w0 = __ldg(w + e0), w1 = __ldg(w + e1);
    ull a0 = (1ULL << 40) | (ull)(w0 * 4294967296.0f);
    ull a1 = (1ULL << 40) | (ull)(w1 * 4294967296.0f);
    ull o0 = atomicAdd(&g_pack[c0], a0);
    ull o1 = atomicAdd(&g_pack[c1], a1);
    int p0 = (int)(o0 >> 40);
    int p1 = (int)(o1 >> 40);
    g_sw[(size_t)c0 * CAP + p0] = make_int2(r0, __float_as_int(w0));
    g_sw[(size_t)c1 * CAP + p1] = make_int2(r1, __float_as_int(w1));
}

// ---------------------------------------------------------------------------
// K2: xs = dis * (X @ W), f32x2 register-blocked GEMM (proven).
constexpr int GEMM_TPB = 256;
constexpr int NPB      = 128;
constexpr int KC       = 32;

__global__ __launch_bounds__(GEMM_TPB)
void k_gemm(const float* __restrict__ X, const float* __restrict__ W) {
    __shared__ float sW[F_IN * F_OUT];   // 32 KB
    __shared__ float sX[NPB * KC];       // 16 KB

    const int tid  = threadIdx.x;
    const int g    = tid & 7;
    const int slot = tid >> 3;
    const int nb   = blockIdx.x * NPB;
    const int ln0  = slot * 4;

    for (int i = tid; i < F_IN * F_OUT / 4; i += GEMM_TPB)
        reinterpret_cast<float4*>(sW)[i] = reinterpret_cast<const float4*>(W)[i];

    ull acc[4][4];
    #pragma unroll
    for (int i = 0; i < 4; i++)
        #pragma unroll
        for (int j = 0; j < 4; j++) acc[i][j] = 0ull;

    for (int c = 0; c < F_IN / KC; c++) {
        __syncthreads();
        for (int i = tid; i < NPB * KC / 4; i += GEMM_TPB) {
            int node = i >> 3;
            int kq   = i & 7;
            float4 v = make_float4(0.f, 0.f, 0.f, 0.f);
            int gn = nb + node;
            if (gn < N_NODES)
                v = reinterpret_cast<const float4*>(X)[(size_t)gn * (F_IN / 4) + c * 8 + kq];
            int k0 = kq * 4;
            sX[node * KC + (((k0 + 0) ^ node) & 31)] = v.x;
            sX[node * KC + (((k0 + 1) ^ node) & 31)] = v.y;
            sX[node * KC + (((k0 + 2) ^ node) & 31)] = v.z;
            sX[node * KC + (((k0 + 3) ^ node) & 31)] = v.w;
        }
        __syncthreads();

        #pragma unroll
        for (int kk = 0; kk < KC; kk++) {
            int row = c * KC + kk;
            ulonglong2 wa = reinterpret_cast<ulonglong2*>(sW)[row * 16 + g * 2];
            ulonglong2 wb = reinterpret_cast<ulonglong2*>(sW)[row * 16 + g * 2 + 1];
            #pragma unroll
            for (int i = 0; i < 4; i++) {
                int ln = ln0 + i;
                float x = sX[ln * KC + ((kk ^ ln) & 31)];
                ull xx = pack2(x);
                fma2(acc[i][0], xx, wa.x);
                fma2(acc[i][1], xx, wa.y);
                fma2(acc[i][2], xx, wb.x);
                fma2(acc[i][3], xx, wb.y);
            }
        }
    }

    #pragma unroll
    for (int i = 0; i < 4; i++) {
        int gn = nb + ln0 + i;
        if (gn < N_NODES) {
            float deg = (float)(g_pack[gn] & DEG_MASK) * DEG_SCALE_INV;
            float d = rsqrtf(deg + 1.0f);
            if (g == 0) g_dis[gn] = d;
            ull dd = pack2(d);
            ulonglong2 o0, o1;
            o0.x = mul2(acc[i][0], dd); o0.y = mul2(acc[i][1], dd);
            o1.x = mul2(acc[i][2], dd); o1.y = mul2(acc[i][3], dd);
            reinterpret_cast<ulonglong2*>(g_xs)[(size_t)gn * 16 + g * 2]     = o0;
            reinterpret_cast<ulonglong2*>(g_xs)[(size_t)gn * 16 + g * 2 + 1] = o1;
        }
    }
}

// ---------------------------------------------------------------------------
// K3: gather-reduce + fused epilogue. Half-warp (16 lanes x float4) per node,
// contiguous int2 meta, 4-wide ILP. (R7 body — measured best at 44.3us.)
__global__ __launch_bounds__(256)
void k_agg(const float* __restrict__ b, float* __restrict__ out) {
    int t = blockIdx.x * blockDim.x + threadIdx.x;
    int node = t >> 4;
    int l    = t & 15;
    if (node >= N_NODES) return;

    const int2* bin = g_sw + (size_t)node * CAP;
    const int cnt = (int)(g_pack[node] >> 40);
    const float4* xs4 = reinterpret_cast<const float4*>(g_xs);

    float4 acc = make_float4(0.f, 0.f, 0.f, 0.f);
    int j = 0;
    for (; j + 4 <= cnt; j += 4) {
        int2 e0 = __ldg(bin + j);
        int2 e1 = __ldg(bin + j + 1);
        int2 e2 = __ldg(bin + j + 2);
        int2 e3 = __ldg(bin + j + 3);
        float4 v0 = __ldg(&xs4[(size_t)e0.x * 16 + l]);
        float4 v1 = __ldg(&xs4[(size_t)e1.x * 16 + l]);
        float4 v2 = __ldg(&xs4[(size_t)e2.x * 16 + l]);
        float4 v3 = __ldg(&xs4[(size_t)e3.x * 16 + l]);
        float w0 = __int_as_float(e0.y), w1 = __int_as_float(e1.y);
        float w2 = __int_as_float(e2.y), w3 = __int_as_float(e3.y);
        acc.x = fmaf(w0, v0.x, acc.x); acc.y = fmaf(w0, v0.y, acc.y);
        acc.z = fmaf(w0, v0.z, acc.z); acc.w = fmaf(w0, v0.w, acc.w);
        acc.x = fmaf(w1, v1.x, acc.x); acc.y = fmaf(w1, v1.y, acc.y);
        acc.z = fmaf(w1, v1.z, acc.z); acc.w = fmaf(w1, v1.w, acc.w);
        acc.x = fmaf(w2, v2.x, acc.x); acc.y = fmaf(w2, v2.y, acc.y);
        acc.z = fmaf(w2, v2.z, acc.z); acc.w = fmaf(w2, v2.w, acc.w);
        acc.x = fmaf(w3, v3.x, acc.x); acc.y = fmaf(w3, v3.y, acc.y);
        acc.z = fmaf(w3, v3.z, acc.z); acc.w = fmaf(w3, v3.w, acc.w);
    }
    for (; j < cnt; j++) {
        int2 e = __ldg(bin + j);
        float4 v = __ldg(&xs4[(size_t)e.x * 16 + l]);
        float we = __int_as_float(e.y);
        acc.x = fmaf(we, v.x, acc.x); acc.y = fmaf(we, v.y, acc.y);
        acc.z = fmaf(we, v.z, acc.z); acc.w = fmaf(we, v.w, acc.w);
    }

    float  d  = g_dis[node];
    float4 x  = xs4[(size_t)node * 16 + l];
    float4 bb = reinterpret_cast<const float4*>(b)[l];
    float4 o;
    o.x = fmaxf(fmaf(d, acc.x + x.x, bb.x), 0.f);
    o.y = fmaxf(fmaf(d, acc.y + x.y, bb.y), 0.f);
    o.z = fmaxf(fmaf(d, acc.z + x.z, bb.z), 0.f);
    o.w = fmaxf(fmaf(d, acc.w + x.w, bb.w), 0.f);
    reinterpret_cast<float4*>(out)[(size_t)node * 16 + l] = o;
}

// ---------------------------------------------------------------------------
extern "C" void kernel_launch(void* const* d_in, const int* in_sizes, int n_in,
                              void* d_out, int out_size) {
    const float* X  = (const float*)d_in[0];            // [N, 128]
    const int*   ei = (const int*)d_in[1];              // [2, E]
    const float* w  = (const float*)d_in[2];            // [E]
    const float* W  = (const float*)d_in[3];            // [128, 64]
    const float* b  = (const float*)d_in[4];            // [64]
    float* out = (float*)d_out;                         // [N, 64]

    const int* row = ei;                // sources
    const int* col = ei + N_EDGES;      // targets

    k_init<<<(N_NODES + 255) / 256, 256>>>();
    k_deg <<<(EH + 255) / 256, 256>>>(row, col, w);
    {   int grid = (N_NODES + NPB - 1) / NPB;
        k_gemm<<<grid, GEMM_TPB>>>(X, W); }
    {   long long threads = (long long)N_NODES * 16;
        k_agg<<<(int)((threads + 255) / 256), 256>>>(b, out); }
}

// round 11
// speedup vs baseline: 1.0365x; 1.0103x over previous
#include <cuda_runtime.h>

// GCNConv on GB300: out = relu(D^-1/2 (A+I) D^-1/2 (X W) + b), edge-weighted.
// R11 = R10 + software-pipelined meta stream in k_agg:
//   current batch meta held in regs (2x int4), next batch's meta loads issued
//   BEFORE consuming current gathers -> meta latency hidden under gathers.

constexpr int N_NODES = 100000;
constexpr int N_EDGES = 1600000;
constexpr int F_IN    = 128;
constexpr int F_OUT   = 64;
constexpr int CAP     = 64;       // per-node bin capacity (deg ~ Poisson(16))

typedef unsigned long long ull;

constexpr ull  DEG_MASK = (1ULL << 40) - 1;
constexpr float DEG_SCALE_INV = 1.0f / 4294967296.0f;   // 2^-32

__device__ __align__(16) float g_dis[N_NODES];
__device__ __align__(16) float g_xs[(size_t)N_NODES * F_OUT];
__device__ ull  g_pack[N_NODES];                         // (cnt<<40)|fx_deg
__device__ __align__(16) int2 g_sw[(size_t)N_NODES * CAP];   // 51.2 MB bins

__device__ __forceinline__ ull pack2(float x) {
    ull r; asm("mov.b64 %0, {%1, %1};" : "=l"(r) : "f"(x)); return r;
}
__device__ __forceinline__ void fma2(ull& d, ull a, ull b) {
    asm("fma.rn.f32x2 %0, %1, %2, %0;" : "+l"(d) : "l"(a), "l"(b));
}
__device__ __forceinline__ ull mul2(ull a, ull b) {
    ull r; asm("mul.rn.f32x2 %0, %1, %2;" : "=l"(r) : "l"(a), "l"(b)); return r;
}

// ---------------------------------------------------------------------------
// K0: zero the packed counters.
__global__ void k_init() {
    int i = blockIdx.x * blockDim.x + threadIdx.x;
    if (i < N_NODES) g_pack[i] = 0ULL;
}

// ---------------------------------------------------------------------------
// K1: single edge pass, ONE packed 64-bit atomic per edge.
constexpr int EH = N_EDGES / 2;   // 800000
__global__ void k_deg(const int* __restrict__ row, const int* __restrict__ col,
                      const float* __restrict__ w) {
    int t = blockIdx.x * blockDim.x + threadIdx.x;
    if (t >= EH) return;
    int e0 = t, e1 = t + EH;
    int c0 = __ldg(col + e0), c1 = __ldg(col + e1);
    int r0 = __ldg(row + e0), r1 = __ldg(row + e1);
    float w0 = __ldg(w + e0), w1 = __ldg(w + e1);
    ull a0 = (1ULL << 40) | (ull)(w0 * 4294967296.0f);
    ull a1 = (1ULL << 40) | (ull)(w1 * 4294967296.0f);
    ull o0 = atomicAdd(&g_pack[c0], a0);
    ull o1 = atomicAdd(&g_pack[c1], a1);
    int p0 = (int)(o0 >> 40);
    int p1 = (int)(o1 >> 40);
    g_sw[(size_t)c0 * CAP + p0] = make_int2(r0, __float_as_int(w0));
    g_sw[(size_t)c1 * CAP + p1] = make_int2(r1, __float_as_int(w1));
}

// ---------------------------------------------------------------------------
// K2: xs = dis * (X @ W), f32x2 register-blocked GEMM (proven).
constexpr int GEMM_TPB = 256;
constexpr int NPB      = 128;
constexpr int KC       = 32;

__global__ __launch_bounds__(GEMM_TPB)
void k_gemm(const float* __restrict__ X, const float* __restrict__ W) {
    __shared__ float sW[F_IN * F_OUT];   // 32 KB
    __shared__ float sX[NPB * KC];       // 16 KB

    const int tid  = threadIdx.x;
    const int g    = tid & 7;
    const int slot = tid >> 3;
    const int nb   = blockIdx.x * NPB;
    const int ln0  = slot * 4;

    for (int i = tid; i < F_IN * F_OUT / 4; i += GEMM_TPB)
        reinterpret_cast<float4*>(sW)[i] = reinterpret_cast<const float4*>(W)[i];

    ull acc[4][4];
    #pragma unroll
    for (int i = 0; i < 4; i++)
        #pragma unroll
        for (int j = 0; j < 4; j++) acc[i][j] = 0ull;

    for (int c = 0; c < F_IN / KC; c++) {
        __syncthreads();
        for (int i = tid; i < NPB * KC / 4; i += GEMM_TPB) {
            int node = i >> 3;
            int kq   = i & 7;
            float4 v = make_float4(0.f, 0.f, 0.f, 0.f);
            int gn = nb + node;
            if (gn < N_NODES)
                v = reinterpret_cast<const float4*>(X)[(size_t)gn * (F_IN / 4) + c * 8 + kq];
            int k0 = kq * 4;
            sX[node * KC + (((k0 + 0) ^ node) & 31)] = v.x;
            sX[node * KC + (((k0 + 1) ^ node) & 31)] = v.y;
            sX[node * KC + (((k0 + 2) ^ node) & 31)] = v.z;
            sX[node * KC + (((k0 + 3) ^ node) & 31)] = v.w;
        }
        __syncthreads();

        #pragma unroll
        for (int kk = 0; kk < KC; kk++) {
            int row = c * KC + kk;
            ulonglong2 wa = reinterpret_cast<ulonglong2*>(sW)[row * 16 + g * 2];
            ulonglong2 wb = reinterpret_cast<ulonglong2*>(sW)[row * 16 + g * 2 + 1];
            #pragma unroll
            for (int i = 0; i < 4; i++) {
                int ln = ln0 + i;
                float x = sX[ln * KC + ((kk ^ ln) & 31)];
                ull xx = pack2(x);
                fma2(acc[i][0], xx, wa.x);
                fma2(acc[i][1], xx, wa.y);
                fma2(acc[i][2], xx, wb.x);
                fma2(acc[i][3], xx, wb.y);
            }
        }
    }

    #pragma unroll
    for (int i = 0; i < 4; i++) {
        int gn = nb + ln0 + i;
        if (gn < N_NODES) {
            float deg = (float)(g_pack[gn] & DEG_MASK) * DEG_SCALE_INV;
            float d = rsqrtf(deg + 1.0f);
            if (g == 0) g_dis[gn] = d;
            ull dd = pack2(d);
            ulonglong2 o0, o1;
            o0.x = mul2(acc[i][0], dd); o0.y = mul2(acc[i][1], dd);
            o1.x = mul2(acc[i][2], dd); o1.y = mul2(acc[i][3], dd);
            reinterpret_cast<ulonglong2*>(g_xs)[(size_t)gn * 16 + g * 2]     = o0;
            reinterpret_cast<ulonglong2*>(g_xs)[(size_t)gn * 16 + g * 2 + 1] = o1;
        }
    }
}

// ---------------------------------------------------------------------------
// K3: gather-reduce + fused epilogue. Half-warp (16 lanes x float4) per node.
// 4 edges per batch; meta for batch k+1 loaded (2x int4) before consuming
// batch k's gathers, so meta latency is hidden under gather latency.
__device__ __forceinline__ void agg_batch(
    const float4* xs4, int l, int4 ma, int4 mb, float4& acc) {
    float4 v0 = __ldg(&xs4[(size_t)ma.x * 16 + l]);
    float4 v1 = __ldg(&xs4[(size_t)ma.z * 16 + l]);
    float4 v2 = __ldg(&xs4[(size_t)mb.x * 16 + l]);
    float4 v3 = __ldg(&xs4[(size_t)mb.z * 16 + l]);
    float w0 = __int_as_float(ma.y), w1 = __int_as_float(ma.w);
    float w2 = __int_as_float(mb.y), w3 = __int_as_float(mb.w);
    acc.x = fmaf(w0, v0.x, acc.x); acc.y = fmaf(w0, v0.y, acc.y);
    acc.z = fmaf(w0, v0.z, acc.z); acc.w = fmaf(w0, v0.w, acc.w);
    acc.x = fmaf(w1, v1.x, acc.x); acc.y = fmaf(w1, v1.y, acc.y);
    acc.z = fmaf(w1, v1.z, acc.z); acc.w = fmaf(w1, v1.w, acc.w);
    acc.x = fmaf(w2, v2.x, acc.x); acc.y = fmaf(w2, v2.y, acc.y);
    acc.z = fmaf(w2, v2.z, acc.z); acc.w = fmaf(w2, v2.w, acc.w);
    acc.x = fmaf(w3, v3.x, acc.x); acc.y = fmaf(w3, v3.y, acc.y);
    acc.z = fmaf(w3, v3.z, acc.z); acc.w = fmaf(w3, v3.w, acc.w);
}

__global__ __launch_bounds__(256)
void k_agg(const float* __restrict__ b, float* __restrict__ out) {
    int t = blockIdx.x * blockDim.x + threadIdx.x;
    int node = t >> 4;
    int l    = t & 15;
    if (node >= N_NODES) return;

    const int2* bin = g_sw + (size_t)node * CAP;
    const int cnt = (int)(g_pack[node] >> 40);
    const float4* xs4 = reinterpret_cast<const float4*>(g_xs);

    float4 acc = make_float4(0.f, 0.f, 0.f, 0.f);
    int j = 0;
    if (cnt >= 4) {
        int4 ca = __ldg(reinterpret_cast<const int4*>(bin));
        int4 cb = __ldg(reinterpret_cast<const int4*>(bin + 2));
        for (; j + 8 <= cnt; j += 4) {
            // prefetch next batch's meta before touching current gathers
            int4 na = __ldg(reinterpret_cast<const int4*>(bin + j + 4));
            int4 nb = __ldg(reinterpret_cast<const int4*>(bin + j + 6));
            agg_batch(xs4, l, ca, cb, acc);
            ca = na; cb = nb;
        }
        agg_batch(xs4, l, ca, cb, acc);   // last full batch
        j += 4;
    }
    for (; j < cnt; j++) {
        int2 e = __ldg(bin + j);
        float4 v = __ldg(&xs4[(size_t)e.x * 16 + l]);
        float we = __int_as_float(e.y);
        acc.x = fmaf(we, v.x, acc.x); acc.y = fmaf(we, v.y, acc.y);
        acc.z = fmaf(we, v.z, acc.z); acc.w = fmaf(we, v.w, acc.w);
    }

    float  d  = g_dis[node];
    float4 x  = xs4[(size_t)node * 16 + l];
    float4 bb = reinterpret_cast<const float4*>(b)[l];
    float4 o;
    o.x = fmaxf(fmaf(d, acc.x + x.x, bb.x), 0.f);
    o.y = fmaxf(fmaf(d, acc.y + x.y, bb.y), 0.f);
    o.z = fmaxf(fmaf(d, acc.z + x.z, bb.z), 0.f);
    o.w = fmaxf(fmaf(d, acc.w + x.w, bb.w), 0.f);
    reinterpret_cast<float4*>(out)[(size_t)node * 16 + l] = o;
}

// ---------------------------------------------------------------------------
extern "C" void kernel_launch(void* const* d_in, const int* in_sizes, int n_in,
                              void* d_out, int out_size) {
    const float* X  = (const float*)d_in[0];            // [N, 128]
    const int*   ei = (const int*)d_in[1];              // [2, E]
    const float* w  = (const float*)d_in[2];            // [E]
    const float* W  = (const float*)d_in[3];            // [128, 64]
    const float* b  = (const float*)d_in[4];            // [64]
    float* out = (float*)d_out;                         // [N, 64]

    const int* row = ei;                // sources
    const int* col = ei + N_EDGES;      // targets

    k_init<<<(N_NODES + 255) / 256, 256>>>();
    k_deg <<<(EH + 255) / 256, 256>>>(row, col, w);
    {   int grid = (N_NODES + NPB - 1) / NPB;
        k_gemm<<<grid, GEMM_TPB>>>(X, W); }
    {   long long threads = (long long)N_NODES * 16;
        k_agg<<<(int)((threads + 255) / 256), 256>>>(b, out); }
}

// round 12
// speedup vs baseline: 1.1164x; 1.0771x over previous
#include <cuda_runtime.h>
#include <cuda_fp16.h>

// GCNConv on GB300: out = relu(D^-1/2 (A+I) D^-1/2 (X W) + b), edge-weighted.
// R12 = R11 + fp16 xs storage: gather payload per edge drops 256B -> 128B
// (half the L2 sector traffic of the dominant k_agg gather stream).
// Accumulation stays fp32; fp16 only quantizes the transformed features
// (~2.4e-4 relative, threshold is 1e-3).

constexpr int N_NODES = 100000;
constexpr int N_EDGES = 1600000;
constexpr int F_IN    = 128;
constexpr int F_OUT   = 64;
constexpr int CAP     = 64;       // per-node bin capacity (deg ~ Poisson(16))

typedef unsigned long long ull;

constexpr ull  DEG_MASK = (1ULL << 40) - 1;
constexpr float DEG_SCALE_INV = 1.0f / 4294967296.0f;   // 2^-32

__device__ __align__(16) float g_dis[N_NODES];
__device__ __align__(16) __half g_xsh[(size_t)N_NODES * F_OUT];   // 12.8 MB fp16
__device__ ull  g_pack[N_NODES];                                  // (cnt<<40)|fx_deg
__device__ __align__(16) int2 g_sw[(size_t)N_NODES * CAP];        // 51.2 MB bins

__device__ __forceinline__ ull pack2(float x) {
    ull r; asm("mov.b64 %0, {%1, %1};" : "=l"(r) : "f"(x)); return r;
}
__device__ __forceinline__ void fma2(ull& d, ull a, ull b) {
    asm("fma.rn.f32x2 %0, %1, %2, %0;" : "+l"(d) : "l"(a), "l"(b));
}
__device__ __forceinline__ ull mul2(ull a, ull b) {
    ull r; asm("mul.rn.f32x2 %0, %1, %2;" : "=l"(r) : "l"(a), "l"(b)); return r;
}
__device__ __forceinline__ unsigned f32x2_to_h2(ull v) {
    float lo, hi;
    asm("mov.b64 {%0, %1}, %2;" : "=f"(lo), "=f"(hi) : "l"(v));
    __half2 h = __floats2half2_rn(lo, hi);
    return *reinterpret_cast<unsigned*>(&h);
}
// Load one lane's 4 fp16 features of a node row and widen to float4.
__device__ __forceinline__ float4 ld_xs4(const uint2* xs2, int src, int l) {
    uint2 u = __ldg(&xs2[(size_t)src * 16 + l]);
    __half2 h0 = *reinterpret_cast<__half2*>(&u.x);
    __half2 h1 = *reinterpret_cast<__half2*>(&u.y);
    float2 f0 = __half22float2(h0);
    float2 f1 = __half22float2(h1);
    return make_float4(f0.x, f0.y, f1.x, f1.y);
}

// ---------------------------------------------------------------------------
// K0: zero the packed counters.
__global__ void k_init() {
    int i = blockIdx.x * blockDim.x + threadIdx.x;
    if (i < N_NODES) g_pack[i] = 0ULL;
}

// ---------------------------------------------------------------------------
// K1: single edge pass, ONE packed 64-bit atomic per edge.
constexpr int EH = N_EDGES / 2;   // 800000
__global__ void k_deg(const int* __restrict__ row, const int* __restrict__ col,
                      const float* __restrict__ w) {
    int t = blockIdx.x * blockDim.x + threadIdx.x;
    if (t >= EH) return;
    int e0 = t, e1 = t + EH;
    int c0 = __ldg(col + e0), c1 = __ldg(col + e1);
    int r0 = __ldg(row + e0), r1 = __ldg(row + e1);
    float w0 = __ldg(w + e0), w1 = __ldg(w + e1);
    ull a0 = (1ULL << 40) | (ull)(w0 * 4294967296.0f);
    ull a1 = (1ULL << 40) | (ull)(w1 * 4294967296.0f);
    ull o0 = atomicAdd(&g_pack[c0], a0);
    ull o1 = atomicAdd(&g_pack[c1], a1);
    int p0 = (int)(o0 >> 40);
    int p1 = (int)(o1 >> 40);
    g_sw[(size_t)c0 * CAP + p0] = make_int2(r0, __float_as_int(w0));
    g_sw[(size_t)c1 * CAP + p1] = make_int2(r1, __float_as_int(w1));
}

// ---------------------------------------------------------------------------
// K2: xs = dis * (X @ W), f32x2 register-blocked GEMM; epilogue emits fp16.
constexpr int GEMM_TPB = 256;
constexpr int NPB      = 128;
constexpr int KC       = 32;

__global__ __launch_bounds__(GEMM_TPB)
void k_gemm(const float* __restrict__ X, const float* __restrict__ W) {
    __shared__ float sW[F_IN * F_OUT];   // 32 KB
    __shared__ float sX[NPB * KC];       // 16 KB

    const int tid  = threadIdx.x;
    const int g    = tid & 7;
    const int slot = tid >> 3;
    const int nb   = blockIdx.x * NPB;
    const int ln0  = slot * 4;

    for (int i = tid; i < F_IN * F_OUT / 4; i += GEMM_TPB)
        reinterpret_cast<float4*>(sW)[i] = reinterpret_cast<const float4*>(W)[i];

    ull acc[4][4];
    #pragma unroll
    for (int i = 0; i < 4; i++)
        #pragma unroll
        for (int j = 0; j < 4; j++) acc[i][j] = 0ull;

    for (int c = 0; c < F_IN / KC; c++) {
        __syncthreads();
        for (int i = tid; i < NPB * KC / 4; i += GEMM_TPB) {
            int node = i >> 3;
            int kq   = i & 7;
            float4 v = make_float4(0.f, 0.f, 0.f, 0.f);
            int gn = nb + node;
            if (gn < N_NODES)
                v = reinterpret_cast<const float4*>(X)[(size_t)gn * (F_IN / 4) + c * 8 + kq];
            int k0 = kq * 4;
            sX[node * KC + (((k0 + 0) ^ node) & 31)] = v.x;
            sX[node * KC + (((k0 + 1) ^ node) & 31)] = v.y;
            sX[node * KC + (((k0 + 2) ^ node) & 31)] = v.z;
            sX[node * KC + (((k0 + 3) ^ node) & 31)] = v.w;
        }
        __syncthreads();

        #pragma unroll
        for (int kk = 0; kk < KC; kk++) {
            int row = c * KC + kk;
            ulonglong2 wa = reinterpret_cast<ulonglong2*>(sW)[row * 16 + g * 2];
            ulonglong2 wb = reinterpret_cast<ulonglong2*>(sW)[row * 16 + g * 2 + 1];
            #pragma unroll
            for (int i = 0; i < 4; i++) {
                int ln = ln0 + i;
                float x = sX[ln * KC + ((kk ^ ln) & 31)];
                ull xx = pack2(x);
                fma2(acc[i][0], xx, wa.x);
                fma2(acc[i][1], xx, wa.y);
                fma2(acc[i][2], xx, wb.x);
                fma2(acc[i][3], xx, wb.y);
            }
        }
    }

    // Epilogue: scale by dis, convert to fp16, one uint4 (8 halves) per thread
    // per node -> 8 threads cover the 128B row, fully coalesced.
    #pragma unroll
    for (int i = 0; i < 4; i++) {
        int gn = nb + ln0 + i;
        if (gn < N_NODES) {
            float deg = (float)(g_pack[gn] & DEG_MASK) * DEG_SCALE_INV;
            float d = rsqrtf(deg + 1.0f);
            if (g == 0) g_dis[gn] = d;
            ull dd = pack2(d);
            uint4 hv;
            hv.x = f32x2_to_h2(mul2(acc[i][0], dd));
            hv.y = f32x2_to_h2(mul2(acc[i][1], dd));
            hv.z = f32x2_to_h2(mul2(acc[i][2], dd));
            hv.w = f32x2_to_h2(mul2(acc[i][3], dd));
            reinterpret_cast<uint4*>(g_xsh)[(size_t)gn * 8 + g] = hv;
        }
    }
}

// ---------------------------------------------------------------------------
// K3: gather-reduce + fused epilogue. Half-warp (16 lanes x 4 fp16 feats) per
// node; pipelined meta (2x int4 per 4-edge batch, next batch prefetched).
__device__ __forceinline__ void agg_batch(
    const uint2* xs2, int l, int4 ma, int4 mb, float4& acc) {
    float4 v0 = ld_xs4(xs2, ma.x, l);
    float4 v1 = ld_xs4(xs2, ma.z, l);
    float4 v2 = ld_xs4(xs2, mb.x, l);
    float4 v3 = ld_xs4(xs2, mb.z, l);
    float w0 = __int_as_float(ma.y), w1 = __int_as_float(ma.w);
    float w2 = __int_as_float(mb.y), w3 = __int_as_float(mb.w);
    acc.x = fmaf(w0, v0.x, acc.x); acc.y = fmaf(w0, v0.y, acc.y);
    acc.z = fmaf(w0, v0.z, acc.z); acc.w = fmaf(w0, v0.w, acc.w);
    acc.x = fmaf(w1, v1.x, acc.x); acc.y = fmaf(w1, v1.y, acc.y);
    acc.z = fmaf(w1, v1.z, acc.z); acc.w = fmaf(w1, v1.w, acc.w);
    acc.x = fmaf(w2, v2.x, acc.x); acc.y = fmaf(w2, v2.y, acc.y);
    acc.z = fmaf(w2, v2.z, acc.z); acc.w = fmaf(w2, v2.w, acc.w);
    acc.x = fmaf(w3, v3.x, acc.x); acc.y = fmaf(w3, v3.y, acc.y);
    acc.z = fmaf(w3, v3.z, acc.z); acc.w = fmaf(w3, v3.w, acc.w);
}

__global__ __launch_bounds__(256)
void k_agg(const float* __restrict__ b, float* __restrict__ out) {
    int t = blockIdx.x * blockDim.x + threadIdx.x;
    int node = t >> 4;
    int l    = t & 15;
    if (node >= N_NODES) return;

    const int2* bin = g_sw + (size_t)node * CAP;
    const int cnt = (int)(g_pack[node] >> 40);
    const uint2* xs2 = reinterpret_cast<const uint2*>(g_xsh);

    float4 acc = make_float4(0.f, 0.f, 0.f, 0.f);
    int j = 0;
    if (cnt >= 4) {
        int4 ca = __ldg(reinterpret_cast<const int4*>(bin));
        int4 cb = __ldg(reinterpret_cast<const int4*>(bin + 2));
        for (; j + 8 <= cnt; j += 4) {
            int4 na = __ldg(reinterpret_cast<const int4*>(bin + j + 4));
            int4 nb = __ldg(reinterpret_cast<const int4*>(bin + j + 6));
            agg_batch(xs2, l, ca, cb, acc);
            ca = na; cb = nb;
        }
        agg_batch(xs2, l, ca, cb, acc);
        j += 4;
    }
    for (; j < cnt; j++) {
        int2 e = __ldg(bin + j);
        float4 v = ld_xs4(xs2, e.x, l);
        float we = __int_as_float(e.y);
        acc.x = fmaf(we, v.x, acc.x); acc.y = fmaf(we, v.y, acc.y);
        acc.z = fmaf(we, v.z, acc.z); acc.w = fmaf(we, v.w, acc.w);
    }

    float  d  = g_dis[node];
    float4 x  = ld_xs4(xs2, node, l);
    float4 bb = reinterpret_cast<const float4*>(b)[l];
    float4 o;
    o.x = fmaxf(fmaf(d, acc.x + x.x, bb.x), 0.f);
    o.y = fmaxf(fmaf(d, acc.y + x.y, bb.y), 0.f);
    o.z = fmaxf(fmaf(d, acc.z + x.z, bb.z), 0.f);
    o.w = fmaxf(fmaf(d, acc.w + x.w, bb.w), 0.f);
    reinterpret_cast<float4*>(out)[(size_t)node * 16 + l] = o;
}

// ---------------------------------------------------------------------------
extern "C" void kernel_launch(void* const* d_in, const int* in_sizes, int n_in,
                              void* d_out, int out_size) {
    const float* X  = (const float*)d_in[0];            // [N, 128]
    const int*   ei = (const int*)d_in[1];              // [2, E]
    const float* w  = (const float*)d_in[2];            // [E]
    const float* W  = (const float*)d_in[3];            // [128, 64]
    const float* b  = (const float*)d_in[4];            // [64]
    float* out = (float*)d_out;                         // [N, 64]

    const int* row = ei;                // sources
    const int* col = ei + N_EDGES;      // targets

    k_init<<<(N_NODES + 255) / 256, 256>>>();
    k_deg <<<(EH + 255) / 256, 256>>>(row, col, w);
    {   int grid = (N_NODES + NPB - 1) / NPB;
        k_gemm<<<grid, GEMM_TPB>>>(X, W); }
    {   long long threads = (long long)N_NODES * 16;
        k_agg<<<(int)((threads + 255) / 256), 256>>>(b, out); }
}

// round 13
// speedup vs baseline: 1.1555x; 1.0350x over previous
#include <cuda_runtime.h>
#include <cuda_fp16.h>

// GCNConv on GB300: out = relu(D^-1/2 (A+I) D^-1/2 (X W) + b), edge-weighted.
// R13 = R12 + quarter-warp-per-node k_agg: 8 lanes x 8 fp16 features, one
// LDG.128 gather per edge-lane, 4 nodes per warp -> ~2x fewer warp-instrs
// per edge (agg is now issue-bound at 55%, not memory-bound).

constexpr int N_NODES = 100000;
constexpr int N_EDGES = 1600000;
constexpr int F_IN    = 128;
constexpr int F_OUT   = 64;
constexpr int CAP     = 64;       // per-node bin capacity (deg ~ Poisson(16))

typedef unsigned long long ull;

constexpr ull  DEG_MASK = (1ULL << 40) - 1;
constexpr float DEG_SCALE_INV = 1.0f / 4294967296.0f;   // 2^-32

__device__ __align__(16) float g_dis[N_NODES];
__device__ __align__(16) __half g_xsh[(size_t)N_NODES * F_OUT];   // 12.8 MB fp16
__device__ ull  g_pack[N_NODES];                                  // (cnt<<40)|fx_deg
__device__ __align__(16) int2 g_sw[(size_t)N_NODES * CAP];        // 51.2 MB bins

__device__ __forceinline__ ull pack2(float x) {
    ull r; asm("mov.b64 %0, {%1, %1};" : "=l"(r) : "f"(x)); return r;
}
__device__ __forceinline__ void fma2(ull& d, ull a, ull b) {
    asm("fma.rn.f32x2 %0, %1, %2, %0;" : "+l"(d) : "l"(a), "l"(b));
}
__device__ __forceinline__ ull mul2(ull a, ull b) {
    ull r; asm("mul.rn.f32x2 %0, %1, %2;" : "=l"(r) : "l"(a), "l"(b)); return r;
}
__device__ __forceinline__ unsigned f32x2_to_h2(ull v) {
    float lo, hi;
    asm("mov.b64 {%0, %1}, %2;" : "=f"(lo), "=f"(hi) : "l"(v));
    __half2 h = __floats2half2_rn(lo, hi);
    return *reinterpret_cast<unsigned*>(&h);
}
// Accumulate 8 fp16 features (one uint4) scaled by w into two float4 accs.
__device__ __forceinline__ void acc8(uint4 u, float w, float4& a0, float4& a1) {
    float2 f0 = __half22float2(*reinterpret_cast<__half2*>(&u.x));
    float2 f1 = __half22float2(*reinterpret_cast<__half2*>(&u.y));
    float2 f2 = __half22float2(*reinterpret_cast<__half2*>(&u.z));
    float2 f3 = __half22float2(*reinterpret_cast<__half2*>(&u.w));
    a0.x = fmaf(w, f0.x, a0.x); a0.y = fmaf(w, f0.y, a0.y);
    a0.z = fmaf(w, f1.x, a0.z); a0.w = fmaf(w, f1.y, a0.w);
    a1.x = fmaf(w, f2.x, a1.x); a1.y = fmaf(w, f2.y, a1.y);
    a1.z = fmaf(w, f3.x, a1.z); a1.w = fmaf(w, f3.y, a1.w);
}

// ---------------------------------------------------------------------------
// K0: zero the packed counters.
__global__ void k_init() {
    int i = blockIdx.x * blockDim.x + threadIdx.x;
    if (i < N_NODES) g_pack[i] = 0ULL;
}

// ---------------------------------------------------------------------------
// K1: single edge pass, ONE packed 64-bit atomic per edge.
constexpr int EH = N_EDGES / 2;   // 800000
__global__ void k_deg(const int* __restrict__ row, const int* __restrict__ col,
                      const float* __restrict__ w) {
    int t = blockIdx.x * blockDim.x + threadIdx.x;
    if (t >= EH) return;
    int e0 = t, e1 = t + EH;
    int c0 = __ldg(col + e0), c1 = __ldg(col + e1);
    int r0 = __ldg(row + e0), r1 = __ldg(row + e1);
    float w0 = __ldg(w + e0), w1 = __ldg(w + e1);
    ull a0 = (1ULL << 40) | (ull)(w0 * 4294967296.0f);
    ull a1 = (1ULL << 40) | (ull)(w1 * 4294967296.0f);
    ull o0 = atomicAdd(&g_pack[c0], a0);
    ull o1 = atomicAdd(&g_pack[c1], a1);
    int p0 = (int)(o0 >> 40);
    int p1 = (int)(o1 >> 40);
    g_sw[(size_t)c0 * CAP + p0] = make_int2(r0, __float_as_int(w0));
    g_sw[(size_t)c1 * CAP + p1] = make_int2(r1, __float_as_int(w1));
}

// ---------------------------------------------------------------------------
// K2: xs = dis * (X @ W), f32x2 register-blocked GEMM; epilogue emits fp16.
constexpr int GEMM_TPB = 256;
constexpr int NPB      = 128;
constexpr int KC       = 32;

__global__ __launch_bounds__(GEMM_TPB)
void k_gemm(const float* __restrict__ X, const float* __restrict__ W) {
    __shared__ float sW[F_IN * F_OUT];   // 32 KB
    __shared__ float sX[NPB * KC];       // 16 KB

    const int tid  = threadIdx.x;
    const int g    = tid & 7;
    const int slot = tid >> 3;
    const int nb   = blockIdx.x * NPB;
    const int ln0  = slot * 4;

    for (int i = tid; i < F_IN * F_OUT / 4; i += GEMM_TPB)
        reinterpret_cast<float4*>(sW)[i] = reinterpret_cast<const float4*>(W)[i];

    ull acc[4][4];
    #pragma unroll
    for (int i = 0; i < 4; i++)
        #pragma unroll
        for (int j = 0; j < 4; j++) acc[i][j] = 0ull;

    for (int c = 0; c < F_IN / KC; c++) {
        __syncthreads();
        for (int i = tid; i < NPB * KC / 4; i += GEMM_TPB) {
            int node = i >> 3;
            int kq   = i & 7;
            float4 v = make_float4(0.f, 0.f, 0.f, 0.f);
            int gn = nb + node;
            if (gn < N_NODES)
                v = reinterpret_cast<const float4*>(X)[(size_t)gn * (F_IN / 4) + c * 8 + kq];
            int k0 = kq * 4;
            sX[node * KC + (((k0 + 0) ^ node) & 31)] = v.x;
            sX[node * KC + (((k0 + 1) ^ node) & 31)] = v.y;
            sX[node * KC + (((k0 + 2) ^ node) & 31)] = v.z;
            sX[node * KC + (((k0 + 3) ^ node) & 31)] = v.w;
        }
        __syncthreads();

        #pragma unroll
        for (int kk = 0; kk < KC; kk++) {
            int row = c * KC + kk;
            ulonglong2 wa = reinterpret_cast<ulonglong2*>(sW)[row * 16 + g * 2];
            ulonglong2 wb = reinterpret_cast<ulonglong2*>(sW)[row * 16 + g * 2 + 1];
            #pragma unroll
            for (int i = 0; i < 4; i++) {
                int ln = ln0 + i;
                float x = sX[ln * KC + ((kk ^ ln) & 31)];
                ull xx = pack2(x);
                fma2(acc[i][0], xx, wa.x);
                fma2(acc[i][1], xx, wa.y);
                fma2(acc[i][2], xx, wb.x);
                fma2(acc[i][3], xx, wb.y);
            }
        }
    }

    #pragma unroll
    for (int i = 0; i < 4; i++) {
        int gn = nb + ln0 + i;
        if (gn < N_NODES) {
            float deg = (float)(g_pack[gn] & DEG_MASK) * DEG_SCALE_INV;
            float d = rsqrtf(deg + 1.0f);
            if (g == 0) g_dis[gn] = d;
            ull dd = pack2(d);
            uint4 hv;
            hv.x = f32x2_to_h2(mul2(acc[i][0], dd));
            hv.y = f32x2_to_h2(mul2(acc[i][1], dd));
            hv.z = f32x2_to_h2(mul2(acc[i][2], dd));
            hv.w = f32x2_to_h2(mul2(acc[i][3], dd));
            reinterpret_cast<uint4*>(g_xsh)[(size_t)gn * 8 + g] = hv;
        }
    }
}

// ---------------------------------------------------------------------------
// K3: quarter-warp gather-reduce + fused epilogue.
// node = t>>3, q = t&7 (8 fp16 features per lane, one uint4 gather per edge).
// 4 nodes per warp; per-group loop divergence only (no warp collectives).
// Tail edges beyond cnt are select-clamped to (src=0, w=0) — bin slots are
// in-bounds (CAP=64) so reads are safe, and w=0 nullifies them.
__global__ __launch_bounds__(256)
void k_agg(const float* __restrict__ b, float* __restrict__ out) {
    int t = blockIdx.x * blockDim.x + threadIdx.x;
    int node = t >> 3;
    int q    = t & 7;
    if (node >= N_NODES) return;

    const int2* bin = g_sw + (size_t)node * CAP;
    const int cnt = (int)(g_pack[node] >> 40);
    const uint4* xsu = reinterpret_cast<const uint4*>(g_xsh);

    float4 a0 = make_float4(0.f, 0.f, 0.f, 0.f);
    float4 a1 = make_float4(0.f, 0.f, 0.f, 0.f);

    for (int j = 0; j < cnt; j += 4) {
        int4 ma = __ldg(reinterpret_cast<const int4*>(bin + j));
        int4 mb = __ldg(reinterpret_cast<const int4*>(bin + j + 2));
        bool v1 = (j + 1) < cnt, v2 = (j + 2) < cnt, v3 = (j + 3) < cnt;
        int   s0 = ma.x;
        int   s1 = v1 ? ma.z : 0;
        int   s2 = v2 ? mb.x : 0;
        int   s3 = v3 ? mb.z : 0;
        float w0 = __int_as_float(ma.y);
        float w1 = v1 ? __int_as_float(ma.w) : 0.f;
        float w2 = v2 ? __int_as_float(mb.y) : 0.f;
        float w3 = v3 ? __int_as_float(mb.w) : 0.f;
        uint4 u0 = __ldg(&xsu[(size_t)s0 * 8 + q]);
        uint4 u1 = __ldg(&xsu[(size_t)s1 * 8 + q]);
        uint4 u2 = __ldg(&xsu[(size_t)s2 * 8 + q]);
        uint4 u3 = __ldg(&xsu[(size_t)s3 * 8 + q]);
        acc8(u0, w0, a0, a1);
        acc8(u1, w1, a0, a1);
        acc8(u2, w2, a0, a1);
        acc8(u3, w3, a0, a1);
    }

    // Self-loop + bias + relu.
    float d = g_dis[node];
    uint4 us = __ldg(&xsu[(size_t)node * 8 + q]);
    float4 x0 = make_float4(0.f, 0.f, 0.f, 0.f);
    float4 x1 = make_float4(0.f, 0.f, 0.f, 0.f);
    acc8(us, 1.0f, x0, x1);
    const float4* b4 = reinterpret_cast<const float4*>(b);
    float4 bb0 = __ldg(&b4[q * 2]);
    float4 bb1 = __ldg(&b4[q * 2 + 1]);
    float4 o0, o1;
    o0.x = fmaxf(fmaf(d, a0.x + x0.x, bb0.x), 0.f);
    o0.y = fmaxf(fmaf(d, a0.y + x0.y, bb0.y), 0.f);
    o0.z = fmaxf(fmaf(d, a0.z + x0.z, bb0.z), 0.f);
    o0.w = fmaxf(fmaf(d, a0.w + x0.w, bb0.w), 0.f);
    o1.x = fmaxf(fmaf(d, a1.x + x1.x, bb1.x), 0.f);
    o1.y = fmaxf(fmaf(d, a1.y + x1.y, bb1.y), 0.f);
    o1.z = fmaxf(fmaf(d, a1.z + x1.z, bb1.z), 0.f);
    o1.w = fmaxf(fmaf(d, a1.w + x1.w, bb1.w), 0.f);
    float4* out4 = reinterpret_cast<float4*>(out);
    out4[(size_t)node * 16 + q * 2]     = o0;
    out4[(size_t)node * 16 + q * 2 + 1] = o1;
}

// ---------------------------------------------------------------------------
extern "C" void kernel_launch(void* const* d_in, const int* in_sizes, int n_in,
                              void* d_out, int out_size) {
    const float* X  = (const float*)d_in[0];            // [N, 128]
    const int*   ei = (const int*)d_in[1];              // [2, E]
    const float* w  = (const float*)d_in[2];            // [E]
    const float* W  = (const float*)d_in[3];            // [128, 64]
    const float* b  = (const float*)d_in[4];            // [64]
    float* out = (float*)d_out;                         // [N, 64]

    const int* row = ei;                // sources
    const int* col = ei + N_EDGES;      // targets

    k_init<<<(N_NODES + 255) / 256, 256>>>();
    k_deg <<<(EH + 255) / 256, 256>>>(row, col, w);
    {   int grid = (N_NODES + NPB - 1) / NPB;
        k_gemm<<<grid, GEMM_TPB>>>(X, W); }
    {   long long threads = (long long)N_NODES * 8;
        k_agg<<<(int)((threads + 255) / 256), 256>>>(b, out); }
}